// round 1
// baseline (speedup 1.0000x reference)
#include <cuda_runtime.h>
#include <math.h>

// Problem shape (fixed for this problem instance)
#define Bb  4
#define Kk  8192
#define Dd  1024
#define Mm  (Bb * Kk)          // 32768 rows of the GEMM
#define NCH 32                 // scan chunks along K
#define LCH (Kk / NCH)         // 256 steps per chunk
#define CHN (Bb * Dd)          // 4096 independent channels

// Scratch (allocation-free rule: __device__ globals)
__device__ float g_lam[(size_t)Mm * Dd];   // 128 MiB: sigmoid(X W^T + b)
__device__ float g_A[NCH * CHN];           // per-chunk product of lam
__device__ float g_S[NCH * CHN];           // per-chunk local scan result (s0 = 0)
__device__ float g_P[NCH * CHN];           // per-chunk incoming prefix state

// ---------------------------------------------------------------------------
// Kernel 1: lam = sigmoid(X @ W^T + b)
// X: [Mm, Dd] row-major, W: [Dd, Dd] row-major (reduction along last dim of both)
// Classic 128x128x16 SIMT tile, 256 threads, 8x8 microtile per thread.
// ---------------------------------------------------------------------------
__global__ __launch_bounds__(256) void gemm_sigmoid_k(
    const float* __restrict__ X,
    const float* __restrict__ W,
    const float* __restrict__ bias)
{
    __shared__ float As[16][128];
    __shared__ float Bs[16][128];

    const int tid = threadIdx.x;
    const int tx  = tid & 15;        // 16 thread cols
    const int ty  = tid >> 4;        // 16 thread rows
    const int m0  = blockIdx.y * 128;
    const int n0  = blockIdx.x * 128;

    float acc[8][8];
    #pragma unroll
    for (int i = 0; i < 8; i++)
        #pragma unroll
        for (int j = 0; j < 8; j++)
            acc[i][j] = 0.0f;

    for (int k0 = 0; k0 < Dd; k0 += 16) {
        // Load A & B tiles: 128 rows x 16 k each = 512 float4 per tile.
        #pragma unroll
        for (int l = 0; l < 2; l++) {
            int t  = tid + l * 256;
            int r  = t >> 2;
            int c4 = (t & 3) * 4;
            float4 va = *(const float4*)&X[(size_t)(m0 + r) * Dd + k0 + c4];
            As[c4 + 0][r] = va.x; As[c4 + 1][r] = va.y;
            As[c4 + 2][r] = va.z; As[c4 + 3][r] = va.w;
            float4 vb = *(const float4*)&W[(size_t)(n0 + r) * Dd + k0 + c4];
            Bs[c4 + 0][r] = vb.x; Bs[c4 + 1][r] = vb.y;
            Bs[c4 + 2][r] = vb.z; Bs[c4 + 3][r] = vb.w;
        }
        __syncthreads();

        #pragma unroll
        for (int k = 0; k < 16; k++) {
            float a[8], b[8];
            #pragma unroll
            for (int i = 0; i < 8; i++) a[i] = As[k][ty * 8 + i];
            #pragma unroll
            for (int j = 0; j < 8; j++) b[j] = Bs[k][tx * 8 + j];
            #pragma unroll
            for (int i = 0; i < 8; i++)
                #pragma unroll
                for (int j = 0; j < 8; j++)
                    acc[i][j] = fmaf(a[i], b[j], acc[i][j]);
        }
        __syncthreads();
    }

    // Epilogue: add bias, sigmoid, store lam.
    #pragma unroll
    for (int i = 0; i < 8; i++) {
        const int m = m0 + ty * 8 + i;
        #pragma unroll
        for (int j = 0; j < 8; j++) {
            const int n = n0 + tx * 8 + j;
            float z = acc[i][j] + bias[n];
            g_lam[(size_t)m * Dd + n] = 1.0f / (1.0f + __expf(-z));
        }
    }
}

// ---------------------------------------------------------------------------
// Scan phase 1: per (channel, chunk) compute A = prod(lam), S = local scan(s0=0)
// Linear recurrence: s_out = A * s_in + S.
// Threads cover consecutive d -> fully coalesced 128B lines per warp per step.
// ---------------------------------------------------------------------------
__global__ __launch_bounds__(256) void scan_phase1(const float* __restrict__ X)
{
    const int d = blockIdx.x * 256 + threadIdx.x;
    const int b = blockIdx.y;
    const int c = blockIdx.z;
    size_t base = ((size_t)(b * Kk + c * LCH)) * Dd + d;

    float s = 0.0f, A = 1.0f;
    #pragma unroll 8
    for (int k = 0; k < LCH; k++) {
        size_t idx = base + (size_t)k * Dd;
        float lam = g_lam[idx];
        float xv  = X[idx];
        s = fmaf(lam, s - xv, xv);   // s = lam*s + (1-lam)*x
        A *= lam;
    }
    const int ch = b * Dd + d;
    g_A[c * CHN + ch] = A;
    g_S[c * CHN + ch] = s;
}

// ---------------------------------------------------------------------------
// Scan phase 2: sequential combine of 32 chunk summaries per channel (tiny).
// ---------------------------------------------------------------------------
__global__ __launch_bounds__(256) void scan_phase2()
{
    const int ch = blockIdx.x * 256 + threadIdx.x;
    float s = 0.0f;
    #pragma unroll
    for (int c = 0; c < NCH; c++) {
        g_P[c * CHN + ch] = s;
        s = fmaf(g_A[c * CHN + ch], s, g_S[c * CHN + ch]);
    }
}

// ---------------------------------------------------------------------------
// Scan phase 3: re-scan each chunk starting from its prefix; write output.
// ---------------------------------------------------------------------------
__global__ __launch_bounds__(256) void scan_phase3(const float* __restrict__ X,
                                                   float* __restrict__ out)
{
    const int d = blockIdx.x * 256 + threadIdx.x;
    const int b = blockIdx.y;
    const int c = blockIdx.z;
    const int ch = b * Dd + d;
    size_t base = ((size_t)(b * Kk + c * LCH)) * Dd + d;

    float s = g_P[c * CHN + ch];
    #pragma unroll 8
    for (int k = 0; k < LCH; k++) {
        size_t idx = base + (size_t)k * Dd;
        float lam = g_lam[idx];
        float xv  = X[idx];
        s = fmaf(lam, s - xv, xv);
        out[idx] = s;
    }
}

// ---------------------------------------------------------------------------
extern "C" void kernel_launch(void* const* d_in, const int* in_sizes, int n_in,
                              void* d_out, int out_size)
{
    const float* X    = (const float*)d_in[0];  // [B,K,D]
    const float* W    = (const float*)d_in[1];  // [D,D]
    const float* bias = (const float*)d_in[2];  // [D]
    float* out        = (float*)d_out;          // [B,K,D]

    dim3 gemm_grid(Dd / 128, Mm / 128);         // (8, 256)
    gemm_sigmoid_k<<<gemm_grid, 256>>>(X, W, bias);

    dim3 scan_grid(Dd / 256, Bb, NCH);          // (4, 4, 32)
    scan_phase1<<<scan_grid, 256>>>(X);
    scan_phase2<<<CHN / 256, 256>>>();
    scan_phase3<<<scan_grid, 256>>>(X, out);
}

// round 2
// speedup vs baseline: 2.2518x; 2.2518x over previous
#include <cuda_runtime.h>
#include <math.h>

// Problem shape (fixed)
#define Bb  4
#define Kk  8192
#define Dd  1024
#define Mm  (Bb * Kk)          // 32768 GEMM rows
#define NCH 32                 // scan chunks along K
#define LCH (Kk / NCH)         // 256 steps per chunk
#define CHN (Bb * Dd)          // 4096 independent channels

// Scratch (allocation-free rule: __device__ globals)
__device__ float g_lam[(size_t)Mm * Dd];   // 128 MiB
__device__ float g_A[NCH * CHN];
__device__ float g_S[NCH * CHN];
__device__ float g_P[NCH * CHN];

// ---------------------------------------------------------------------------
// TF32 tensor-core GEMM + sigmoid epilogue:  g_lam = sigmoid(X @ W^T + b)
// Block 128x128, BK=16, 4 warps, 64x64 warp tile, m16n8k8 tf32 HMMA.
// ---------------------------------------------------------------------------
#define BM 128
#define BN 128
#define BK 16
#define SPITCH 136   // 136 mod 32 == 8 -> conflict-free fragment LDS

__device__ __forceinline__ unsigned f2tf32(float f) {
    unsigned u;
    asm("cvt.rna.tf32.f32 %0, %1;" : "=r"(u) : "f"(f));
    return u;
}

__device__ __forceinline__ void mma_tf32(float* d, const unsigned* a, const unsigned* b) {
    asm volatile(
        "mma.sync.aligned.m16n8k8.row.col.f32.tf32.tf32.f32 "
        "{%0,%1,%2,%3}, {%4,%5,%6,%7}, {%8,%9}, {%0,%1,%2,%3};\n"
        : "+f"(d[0]), "+f"(d[1]), "+f"(d[2]), "+f"(d[3])
        : "r"(a[0]), "r"(a[1]), "r"(a[2]), "r"(a[3]), "r"(b[0]), "r"(b[1]));
}

__global__ __launch_bounds__(128) void gemm_sigmoid_tc(
    const float* __restrict__ X,
    const float* __restrict__ W,
    const float* __restrict__ bias)
{
    __shared__ unsigned As[2][BK][SPITCH];
    __shared__ unsigned Bs[2][BK][SPITCH];

    const int tid  = threadIdx.x;
    const int lane = tid & 31;
    const int wid  = tid >> 5;          // 4 warps
    const int wm0  = (wid & 1) * 64;    // warp m-offset in block
    const int wn0  = (wid >> 1) * 64;   // warp n-offset in block
    const int g    = lane >> 2;         // 0..7
    const int q    = lane & 3;          // 0..3
    const int m0b  = blockIdx.y * BM;
    const int n0b  = blockIdx.x * BN;

    float acc[4][8][4];
    #pragma unroll
    for (int mi = 0; mi < 4; mi++)
        #pragma unroll
        for (int ni = 0; ni < 8; ni++)
            #pragma unroll
            for (int r = 0; r < 4; r++)
                acc[mi][ni][r] = 0.0f;

    // gmem load helper indices: 512 float4 per matrix per stage / 128 threads = 4 each
    // f = tid + i*128 ; row = f>>2 ; kc4 = (f&3)*4
    float4 pa[4], pb[4];

    #pragma unroll
    for (int i = 0; i < 4; i++) {
        int f = tid + i * 128, r = f >> 2, c4 = (f & 3) * 4;
        pa[i] = *(const float4*)&X[(size_t)(m0b + r) * Dd + c4];
        pb[i] = *(const float4*)&W[(size_t)(n0b + r) * Dd + c4];
    }
    // store stage 0
    #pragma unroll
    for (int i = 0; i < 4; i++) {
        int f = tid + i * 128, r = f >> 2, c4 = (f & 3) * 4;
        As[0][c4 + 0][r] = f2tf32(pa[i].x); As[0][c4 + 1][r] = f2tf32(pa[i].y);
        As[0][c4 + 2][r] = f2tf32(pa[i].z); As[0][c4 + 3][r] = f2tf32(pa[i].w);
        Bs[0][c4 + 0][r] = f2tf32(pb[i].x); Bs[0][c4 + 1][r] = f2tf32(pb[i].y);
        Bs[0][c4 + 2][r] = f2tf32(pb[i].z); Bs[0][c4 + 3][r] = f2tf32(pb[i].w);
    }
    __syncthreads();

    int buf = 0;
    const int NSTAGE = Dd / BK;   // 64
    for (int kt = 0; kt < NSTAGE; kt++) {
        // prefetch next stage gmem -> regs
        if (kt < NSTAGE - 1) {
            int k0 = (kt + 1) * BK;
            #pragma unroll
            for (int i = 0; i < 4; i++) {
                int f = tid + i * 128, r = f >> 2, c4 = (f & 3) * 4;
                pa[i] = *(const float4*)&X[(size_t)(m0b + r) * Dd + k0 + c4];
                pb[i] = *(const float4*)&W[(size_t)(n0b + r) * Dd + k0 + c4];
            }
        }

        // compute on current buffer: 2 k-fragments (k=0..7, 8..15)
        #pragma unroll
        for (int kf = 0; kf < BK; kf += 8) {
            unsigned af[4][4], bf[8][2];
            #pragma unroll
            for (int mi = 0; mi < 4; mi++) {
                int m = wm0 + mi * 16 + g;
                af[mi][0] = As[buf][kf + q    ][m];
                af[mi][1] = As[buf][kf + q    ][m + 8];
                af[mi][2] = As[buf][kf + q + 4][m];
                af[mi][3] = As[buf][kf + q + 4][m + 8];
            }
            #pragma unroll
            for (int ni = 0; ni < 8; ni++) {
                int n = wn0 + ni * 8 + g;
                bf[ni][0] = Bs[buf][kf + q    ][n];
                bf[ni][1] = Bs[buf][kf + q + 4][n];
            }
            #pragma unroll
            for (int mi = 0; mi < 4; mi++)
                #pragma unroll
                for (int ni = 0; ni < 8; ni++)
                    mma_tf32(acc[mi][ni], af[mi], bf[ni]);
        }

        // store next stage (buf^1 not read since before the last barrier)
        if (kt < NSTAGE - 1) {
            int nb = buf ^ 1;
            #pragma unroll
            for (int i = 0; i < 4; i++) {
                int f = tid + i * 128, r = f >> 2, c4 = (f & 3) * 4;
                As[nb][c4 + 0][r] = f2tf32(pa[i].x); As[nb][c4 + 1][r] = f2tf32(pa[i].y);
                As[nb][c4 + 2][r] = f2tf32(pa[i].z); As[nb][c4 + 3][r] = f2tf32(pa[i].w);
                Bs[nb][c4 + 0][r] = f2tf32(pb[i].x); Bs[nb][c4 + 1][r] = f2tf32(pb[i].y);
                Bs[nb][c4 + 2][r] = f2tf32(pb[i].z); Bs[nb][c4 + 3][r] = f2tf32(pb[i].w);
            }
        }
        __syncthreads();
        buf ^= 1;
    }

    // Epilogue: bias + sigmoid -> g_lam
    #pragma unroll
    for (int ni = 0; ni < 8; ni++) {
        const int c0 = n0b + wn0 + ni * 8 + 2 * q;
        const float b0 = bias[c0];
        const float b1 = bias[c0 + 1];
        #pragma unroll
        for (int mi = 0; mi < 4; mi++) {
            const int r0 = m0b + wm0 + mi * 16 + g;
            float2 v0, v1;
            float z;
            z = acc[mi][ni][0] + b0; v0.x = 1.0f / (1.0f + __expf(-z));
            z = acc[mi][ni][1] + b1; v0.y = 1.0f / (1.0f + __expf(-z));
            z = acc[mi][ni][2] + b0; v1.x = 1.0f / (1.0f + __expf(-z));
            z = acc[mi][ni][3] + b1; v1.y = 1.0f / (1.0f + __expf(-z));
            *(float2*)&g_lam[(size_t)r0 * Dd + c0]       = v0;
            *(float2*)&g_lam[(size_t)(r0 + 8) * Dd + c0] = v1;
        }
    }
}

// ---------------------------------------------------------------------------
// Scan phase 1: per (channel, chunk): A = prod(lam), S = local scan (s0=0)
// ---------------------------------------------------------------------------
__global__ __launch_bounds__(256) void scan_phase1(const float* __restrict__ X)
{
    const int d = blockIdx.x * 256 + threadIdx.x;
    const int b = blockIdx.y;
    const int c = blockIdx.z;
    size_t base = ((size_t)(b * Kk + c * LCH)) * Dd + d;

    float s = 0.0f, A = 1.0f;
    #pragma unroll 8
    for (int k = 0; k < LCH; k++) {
        size_t idx = base + (size_t)k * Dd;
        float lam = g_lam[idx];
        float xv  = X[idx];
        s = fmaf(lam, s - xv, xv);   // s = lam*s + (1-lam)*x
        A *= lam;
    }
    const int ch = b * Dd + d;
    g_A[c * CHN + ch] = A;
    g_S[c * CHN + ch] = s;
}

// ---------------------------------------------------------------------------
// Scan phase 2: sequential combine of 32 chunk summaries per channel (tiny).
// ---------------------------------------------------------------------------
__global__ __launch_bounds__(256) void scan_phase2()
{
    const int ch = blockIdx.x * 256 + threadIdx.x;
    float s = 0.0f;
    #pragma unroll
    for (int c = 0; c < NCH; c++) {
        g_P[c * CHN + ch] = s;
        s = fmaf(g_A[c * CHN + ch], s, g_S[c * CHN + ch]);
    }
}

// ---------------------------------------------------------------------------
// Scan phase 3: re-scan each chunk starting from its prefix; write output.
// ---------------------------------------------------------------------------
__global__ __launch_bounds__(256) void scan_phase3(const float* __restrict__ X,
                                                   float* __restrict__ out)
{
    const int d = blockIdx.x * 256 + threadIdx.x;
    const int b = blockIdx.y;
    const int c = blockIdx.z;
    const int ch = b * Dd + d;
    size_t base = ((size_t)(b * Kk + c * LCH)) * Dd + d;

    float s = g_P[c * CHN + ch];
    #pragma unroll 8
    for (int k = 0; k < LCH; k++) {
        size_t idx = base + (size_t)k * Dd;
        float lam = g_lam[idx];
        float xv  = X[idx];
        s = fmaf(lam, s - xv, xv);
        out[idx] = s;
    }
}

// ---------------------------------------------------------------------------
extern "C" void kernel_launch(void* const* d_in, const int* in_sizes, int n_in,
                              void* d_out, int out_size)
{
    const float* X    = (const float*)d_in[0];  // [B,K,D]
    const float* W    = (const float*)d_in[1];  // [D,D]
    const float* bias = (const float*)d_in[2];  // [D]
    float* out        = (float*)d_out;          // [B,K,D]

    dim3 gemm_grid(Dd / BN, Mm / BM);           // (8, 256)
    gemm_sigmoid_tc<<<gemm_grid, 128>>>(X, W, bias);

    dim3 scan_grid(Dd / 256, Bb, NCH);          // (4, 4, 32)
    scan_phase1<<<scan_grid, 256>>>(X);
    scan_phase2<<<CHN / 256, 256>>>();
    scan_phase3<<<scan_grid, 256>>>(X, out);
}

// round 3
// speedup vs baseline: 2.5614x; 1.1375x over previous
#include <cuda_runtime.h>
#include <math.h>

// Problem shape (fixed)
#define Bb  4
#define Kk  8192
#define Dd  1024
#define Mm  (Bb * Kk)          // 32768 GEMM rows
#define NCH 32                 // scan chunks along K
#define LCH (Kk / NCH)         // 256 steps per chunk
#define CHN (Bb * Dd)          // 4096 independent channels

// Scratch (allocation-free rule: __device__ globals)
__device__ float g_lam[(size_t)Mm * Dd];   // 128 MiB
__device__ float g_A[NCH * CHN];
__device__ float g_S[NCH * CHN];
__device__ float g_P[NCH * CHN];

// ---------------------------------------------------------------------------
// TF32 tensor-core GEMM + sigmoid epilogue:  g_lam = sigmoid(X @ W^T + b)
// 256 threads, BM=128 x BN=256, BK=16, 2x4 warps of 64x64.
// cp.async 4-stage pipeline, raw-f32-as-tf32 (no cvt), pitch-20 smem
// (banks (20g+q) mod 32 all distinct -> conflict-free fragment LDS).
// ---------------------------------------------------------------------------
#define BM 128
#define BN 256
#define BK 16
#define PIT 20                       // smem row pitch in floats
#define NSTG 4                       // pipeline stages
#define A_STG (BM * PIT)             // 2560 floats / stage
#define B_STG (BN * PIT)             // 5120 floats / stage
#define SMEM_FLOATS (NSTG * (A_STG + B_STG))   // 30720 floats = 122880 B

__device__ __forceinline__ void cp16(void* smem_dst, const void* gmem_src) {
    unsigned saddr = (unsigned)__cvta_generic_to_shared(smem_dst);
    asm volatile("cp.async.cg.shared.global [%0], [%1], 16;\n"
                 :: "r"(saddr), "l"(gmem_src));
}
__device__ __forceinline__ void cp_commit() {
    asm volatile("cp.async.commit_group;\n");
}
template <int N>
__device__ __forceinline__ void cp_wait() {
    asm volatile("cp.async.wait_group %0;\n" :: "n"(N));
}

__device__ __forceinline__ void mma_tf32(float* d, const unsigned* a, const unsigned* b) {
    asm volatile(
        "mma.sync.aligned.m16n8k8.row.col.f32.tf32.tf32.f32 "
        "{%0,%1,%2,%3}, {%4,%5,%6,%7}, {%8,%9}, {%0,%1,%2,%3};\n"
        : "+f"(d[0]), "+f"(d[1]), "+f"(d[2]), "+f"(d[3])
        : "r"(a[0]), "r"(a[1]), "r"(a[2]), "r"(a[3]), "r"(b[0]), "r"(b[1]));
}

extern __shared__ float smem[];

__global__ __launch_bounds__(256, 1) void gemm_sigmoid_tc(
    const float* __restrict__ X,
    const float* __restrict__ W,
    const float* __restrict__ bias)
{
    float* As = smem;                 // [NSTG][BM][PIT]
    float* Bs = smem + NSTG * A_STG;  // [NSTG][BN][PIT]

    const int tid  = threadIdx.x;
    const int lane = tid & 31;
    const int wid  = tid >> 5;          // 8 warps: 2 (m) x 4 (n)
    const int wm0  = (wid & 1) * 64;
    const int wn0  = (wid >> 1) * 64;
    const int g    = lane >> 2;         // 0..7
    const int q    = lane & 3;          // 0..3
    const int m0b  = blockIdx.y * BM;
    const int n0b  = blockIdx.x * BN;

    float acc[4][8][4];
    #pragma unroll
    for (int mi = 0; mi < 4; mi++)
        #pragma unroll
        for (int ni = 0; ni < 8; ni++)
            #pragma unroll
            for (int r = 0; r < 4; r++)
                acc[mi][ni][r] = 0.0f;

    // --- async stage loader: 1536 16B-chunks per stage, 6 per thread ---
    // idx < 512  -> A chunk: row = idx>>2 (0..127), c4 = (idx&3)*4
    // idx >= 512 -> B chunk: row = (idx-512)>>2 (0..255)
    auto load_stage = [&](int kt) {
        const int slot = kt & (NSTG - 1);
        const int k0   = kt * BK;
        #pragma unroll
        for (int i = 0; i < 6; i++) {
            int idx = tid + i * 256;
            if (idx < 512) {
                int r = idx >> 2, c4 = (idx & 3) * 4;
                cp16(&As[slot * A_STG + r * PIT + c4],
                     &X[(size_t)(m0b + r) * Dd + k0 + c4]);
            } else {
                int j = idx - 512;
                int r = j >> 2, c4 = (j & 3) * 4;
                cp16(&Bs[slot * B_STG + r * PIT + c4],
                     &W[(size_t)(n0b + r) * Dd + k0 + c4]);
            }
        }
        cp_commit();
    };

    const int NSTAGE = Dd / BK;   // 64
    // prologue: stages 0..2 in flight
    load_stage(0);
    load_stage(1);
    load_stage(2);

    for (int kt = 0; kt < NSTAGE; kt++) {
        cp_wait<2>();          // stage kt landed
        __syncthreads();       // also: everyone done reading slot (kt+3)&3 == kt-1

        if (kt + 3 < NSTAGE) load_stage(kt + 3);

        const int slot = kt & (NSTG - 1);
        const float* Asl = &As[slot * A_STG];
        const float* Bsl = &Bs[slot * B_STG];

        #pragma unroll
        for (int kf = 0; kf < BK; kf += 8) {
            unsigned af[4][4], bf[8][2];
            #pragma unroll
            for (int mi = 0; mi < 4; mi++) {
                int base = (wm0 + mi * 16 + g) * PIT + kf + q;
                af[mi][0] = __float_as_uint(Asl[base]);
                af[mi][1] = __float_as_uint(Asl[base + 8 * PIT]);
                af[mi][2] = __float_as_uint(Asl[base + 4]);
                af[mi][3] = __float_as_uint(Asl[base + 8 * PIT + 4]);
            }
            #pragma unroll
            for (int ni = 0; ni < 8; ni++) {
                int base = (wn0 + ni * 8 + g) * PIT + kf + q;
                bf[ni][0] = __float_as_uint(Bsl[base]);
                bf[ni][1] = __float_as_uint(Bsl[base + 4]);
            }
            #pragma unroll
            for (int mi = 0; mi < 4; mi++)
                #pragma unroll
                for (int ni = 0; ni < 8; ni++)
                    mma_tf32(acc[mi][ni], af[mi], bf[ni]);
        }
        __syncthreads();
    }

    // Epilogue: bias + sigmoid -> g_lam
    #pragma unroll
    for (int ni = 0; ni < 8; ni++) {
        const int c0 = n0b + wn0 + ni * 8 + 2 * q;
        const float b0 = bias[c0];
        const float b1 = bias[c0 + 1];
        #pragma unroll
        for (int mi = 0; mi < 4; mi++) {
            const int r0 = m0b + wm0 + mi * 16 + g;
            float2 v0, v1;
            float z;
            z = acc[mi][ni][0] + b0; v0.x = 1.0f / (1.0f + __expf(-z));
            z = acc[mi][ni][1] + b1; v0.y = 1.0f / (1.0f + __expf(-z));
            z = acc[mi][ni][2] + b0; v1.x = 1.0f / (1.0f + __expf(-z));
            z = acc[mi][ni][3] + b1; v1.y = 1.0f / (1.0f + __expf(-z));
            *(float2*)&g_lam[(size_t)r0 * Dd + c0]       = v0;
            *(float2*)&g_lam[(size_t)(r0 + 8) * Dd + c0] = v1;
        }
    }
}

// ---------------------------------------------------------------------------
// Scan phase 1: per (channel, chunk): A = prod(lam), S = local scan (s0=0)
// ---------------------------------------------------------------------------
__global__ __launch_bounds__(256) void scan_phase1(const float* __restrict__ X)
{
    const int d = blockIdx.x * 256 + threadIdx.x;
    const int b = blockIdx.y;
    const int c = blockIdx.z;
    size_t base = ((size_t)(b * Kk + c * LCH)) * Dd + d;

    float s = 0.0f, A = 1.0f;
    #pragma unroll 8
    for (int k = 0; k < LCH; k++) {
        size_t idx = base + (size_t)k * Dd;
        float lam = g_lam[idx];
        float xv  = X[idx];
        s = fmaf(lam, s - xv, xv);   // s = lam*s + (1-lam)*x
        A *= lam;
    }
    const int ch = b * Dd + d;
    g_A[c * CHN + ch] = A;
    g_S[c * CHN + ch] = s;
}

// ---------------------------------------------------------------------------
// Scan phase 2: sequential combine of 32 chunk summaries per channel (tiny).
// ---------------------------------------------------------------------------
__global__ __launch_bounds__(256) void scan_phase2()
{
    const int ch = blockIdx.x * 256 + threadIdx.x;
    float s = 0.0f;
    #pragma unroll
    for (int c = 0; c < NCH; c++) {
        g_P[c * CHN + ch] = s;
        s = fmaf(g_A[c * CHN + ch], s, g_S[c * CHN + ch]);
    }
}

// ---------------------------------------------------------------------------
// Scan phase 3: re-scan each chunk starting from its prefix; write output.
// ---------------------------------------------------------------------------
__global__ __launch_bounds__(256) void scan_phase3(const float* __restrict__ X,
                                                   float* __restrict__ out)
{
    const int d = blockIdx.x * 256 + threadIdx.x;
    const int b = blockIdx.y;
    const int c = blockIdx.z;
    const int ch = b * Dd + d;
    size_t base = ((size_t)(b * Kk + c * LCH)) * Dd + d;

    float s = g_P[c * CHN + ch];
    #pragma unroll 8
    for (int k = 0; k < LCH; k++) {
        size_t idx = base + (size_t)k * Dd;
        float lam = g_lam[idx];
        float xv  = X[idx];
        s = fmaf(lam, s - xv, xv);
        out[idx] = s;
    }
}

// ---------------------------------------------------------------------------
extern "C" void kernel_launch(void* const* d_in, const int* in_sizes, int n_in,
                              void* d_out, int out_size)
{
    const float* X    = (const float*)d_in[0];  // [B,K,D]
    const float* W    = (const float*)d_in[1];  // [D,D]
    const float* bias = (const float*)d_in[2];  // [D]
    float* out        = (float*)d_out;          // [B,K,D]

    cudaFuncSetAttribute(gemm_sigmoid_tc,
                         cudaFuncAttributeMaxDynamicSharedMemorySize,
                         SMEM_FLOATS * (int)sizeof(float));

    dim3 gemm_grid(Dd / BN, Mm / BM);           // (4, 256)
    gemm_sigmoid_tc<<<gemm_grid, 256, SMEM_FLOATS * sizeof(float)>>>(X, W, bias);

    dim3 scan_grid(Dd / 256, Bb, NCH);          // (4, 4, 32)
    scan_phase1<<<scan_grid, 256>>>(X);
    scan_phase2<<<CHN / 256, 256>>>();
    scan_phase3<<<scan_grid, 256>>>(X, out);
}

// round 5
// speedup vs baseline: 3.7181x; 1.4516x over previous
#include <cuda_runtime.h>
#include <cuda_fp16.h>
#include <cstdint>
#include <math.h>

// Problem shape (fixed)
#define Bb  4
#define Kk  8192
#define Dd  1024
#define Mm  (Bb * Kk)          // 32768 GEMM rows
#define NCH 32                 // scan chunks along K
#define LCH (Kk / NCH)         // 256 steps per chunk
#define CHN (Bb * Dd)          // 4096 independent channels

// Scratch (allocation-free rule: __device__ globals)
__device__ float  g_lam[(size_t)Mm * Dd];     // 128 MiB
__device__ __half g_Xh[(size_t)Mm * Dd];      // 64 MiB fp16 X
__device__ __half g_Wh[(size_t)Dd * Dd];      // 2 MiB fp16 W
__device__ float  g_A[NCH * CHN];
__device__ float  g_S[NCH * CHN];
__device__ float  g_P[NCH * CHN];

// ---------------------------------------------------------------------------
// f32 -> f16 conversion pass (round-to-nearest), vectorized 4-wide.
// ---------------------------------------------------------------------------
__global__ __launch_bounds__(256) void f2h_kernel(const float4* __restrict__ src,
                                                  uint2* __restrict__ dst, int n4)
{
    int i = blockIdx.x * blockDim.x + threadIdx.x;
    const int stride = gridDim.x * blockDim.x;
    for (; i < n4; i += stride) {
        float4 v = src[i];
        __half2 h0 = __floats2half2_rn(v.x, v.y);
        __half2 h1 = __floats2half2_rn(v.z, v.w);
        uint2 o;
        o.x = *reinterpret_cast<unsigned*>(&h0);
        o.y = *reinterpret_cast<unsigned*>(&h1);
        dst[i] = o;
    }
}

// ---------------------------------------------------------------------------
// FP16 tensor-core GEMM + sigmoid epilogue:  g_lam = sigmoid(X @ W^T + b)
// 256 threads, BM=128 x BN=256, BK=32, 2x4 warps of 64x64, m16n8k16 fp16 HMMA,
// 4-stage cp.async pipeline, pitch-40-halves smem (banks (20g+q)%32 distinct).
// ---------------------------------------------------------------------------
#define BM 128
#define BN 256
#define BK 32
#define PITH 40                          // smem row pitch in halves (80 B)
#define NSTG 4
#define A_STGH (BM * PITH)               // 5120 halves / stage
#define B_STGH (BN * PITH)               // 10240 halves / stage
#define SMEM_HALVES (NSTG * (A_STGH + B_STGH))   // 61440 halves = 122880 B
#define NKT (Dd / BK)                    // 32 k-stages

__device__ __forceinline__ void cp16s(uint32_t smem_dst, const void* gmem_src) {
    asm volatile("cp.async.cg.shared.global [%0], [%1], 16;\n"
                 :: "r"(smem_dst), "l"(gmem_src));
}
__device__ __forceinline__ void cp_commit() {
    asm volatile("cp.async.commit_group;\n");
}
template <int N>
__device__ __forceinline__ void cp_wait() {
    asm volatile("cp.async.wait_group %0;\n" :: "n"(N));
}
__device__ __forceinline__ void mma_f16(float* d, const unsigned* a, const unsigned* b) {
    asm volatile(
        "mma.sync.aligned.m16n8k16.row.col.f32.f16.f16.f32 "
        "{%0,%1,%2,%3}, {%4,%5,%6,%7}, {%8,%9}, {%0,%1,%2,%3};\n"
        : "+f"(d[0]), "+f"(d[1]), "+f"(d[2]), "+f"(d[3])
        : "r"(a[0]), "r"(a[1]), "r"(a[2]), "r"(a[3]), "r"(b[0]), "r"(b[1]));
}

extern __shared__ __half smemh[];

__global__ __launch_bounds__(256, 1) void gemm_sigmoid_f16(
    const float* __restrict__ bias)
{
    __half* As = smemh;                  // [NSTG][BM][PITH]
    __half* Bs = smemh + NSTG * A_STGH;  // [NSTG][BN][PITH]

    const int tid  = threadIdx.x;
    const int lane = tid & 31;
    const int wid  = tid >> 5;           // 8 warps: 2 (m) x 4 (n)
    const int wm0  = (wid & 1) * 64;
    const int wn0  = (wid >> 1) * 64;
    const int g    = lane >> 2;          // 0..7
    const int q    = lane & 3;           // 0..3
    const int m0b  = blockIdx.y * BM;
    const int n0b  = blockIdx.x * BN;

    const uint32_t sA = (uint32_t)__cvta_generic_to_shared(As);
    const uint32_t sB = (uint32_t)__cvta_generic_to_shared(Bs);

    float acc[4][8][4];
    #pragma unroll
    for (int mi = 0; mi < 4; mi++)
        #pragma unroll
        for (int ni = 0; ni < 8; ni++)
            #pragma unroll
            for (int r = 0; r < 4; r++)
                acc[mi][ni][r] = 0.0f;

    // --- async stage loader: A 512 + B 1024 = 1536 16B-chunks, 6/thread ---
    auto load_stage = [&](int kt) {
        const int slot = kt & (NSTG - 1);
        const int k0   = kt * BK;
        const uint32_t abase = sA + slot * A_STGH * 2;
        const uint32_t bbase = sB + slot * B_STGH * 2;
        #pragma unroll
        for (int i = 0; i < 6; i++) {
            int idx = tid + i * 256;
            if (idx < 512) {                   // A: 128 rows x 4 chunks (8 halves)
                int r = idx >> 2, c = idx & 3;
                cp16s(abase + (r * PITH + c * 8) * 2,
                      &g_Xh[(size_t)(m0b + r) * Dd + k0 + c * 8]);
            } else {                           // B: 256 rows x 4 chunks
                int j = idx - 512;
                int r = j >> 2, c = j & 3;
                cp16s(bbase + (r * PITH + c * 8) * 2,
                      &g_Wh[(size_t)(n0b + r) * Dd + k0 + c * 8]);
            }
        }
        cp_commit();
    };

    load_stage(0);
    load_stage(1);
    load_stage(2);

    for (int kt = 0; kt < NKT; kt++) {
        if (kt + 3 < NKT) load_stage(kt + 3);
        cp_wait<3>();           // stage kt landed
        __syncthreads();

        const int slot = kt & (NSTG - 1);
        const __half* Asl = &As[slot * A_STGH];
        const __half* Bsl = &Bs[slot * B_STGH];

        #pragma unroll
        for (int kf = 0; kf < BK; kf += 16) {
            unsigned af[4][4], bf[8][2];
            #pragma unroll
            for (int mi = 0; mi < 4; mi++) {
                int base = (wm0 + mi * 16 + g) * PITH + kf + 2 * q;
                af[mi][0] = *(const unsigned*)&Asl[base];
                af[mi][1] = *(const unsigned*)&Asl[base + 8 * PITH];
                af[mi][2] = *(const unsigned*)&Asl[base + 8];
                af[mi][3] = *(const unsigned*)&Asl[base + 8 * PITH + 8];
            }
            #pragma unroll
            for (int ni = 0; ni < 8; ni++) {
                int base = (wn0 + ni * 8 + g) * PITH + kf + 2 * q;
                bf[ni][0] = *(const unsigned*)&Bsl[base];
                bf[ni][1] = *(const unsigned*)&Bsl[base + 8];
            }
            #pragma unroll
            for (int mi = 0; mi < 4; mi++)
                #pragma unroll
                for (int ni = 0; ni < 8; ni++)
                    mma_f16(acc[mi][ni], af[mi], bf[ni]);
        }
        __syncthreads();
    }

    // Epilogue: bias + sigmoid -> g_lam (f32)
    #pragma unroll
    for (int ni = 0; ni < 8; ni++) {
        const int c0 = n0b + wn0 + ni * 8 + 2 * q;
        const float b0 = bias[c0];
        const float b1 = bias[c0 + 1];
        #pragma unroll
        for (int mi = 0; mi < 4; mi++) {
            const int r0 = m0b + wm0 + mi * 16 + g;
            float2 v0, v1;
            float z;
            z = acc[mi][ni][0] + b0; v0.x = 1.0f / (1.0f + __expf(-z));
            z = acc[mi][ni][1] + b1; v0.y = 1.0f / (1.0f + __expf(-z));
            z = acc[mi][ni][2] + b0; v1.x = 1.0f / (1.0f + __expf(-z));
            z = acc[mi][ni][3] + b1; v1.y = 1.0f / (1.0f + __expf(-z));
            *(float2*)&g_lam[(size_t)r0 * Dd + c0]       = v0;
            *(float2*)&g_lam[(size_t)(r0 + 8) * Dd + c0] = v1;
        }
    }
}

// ---------------------------------------------------------------------------
// Scan phase 1: per (channel, chunk): A = prod(lam), S = local scan (s0=0)
// ---------------------------------------------------------------------------
__global__ __launch_bounds__(256) void scan_phase1(const float* __restrict__ X)
{
    const int d = blockIdx.x * 256 + threadIdx.x;
    const int b = blockIdx.y;
    const int c = blockIdx.z;
    size_t base = ((size_t)(b * Kk + c * LCH)) * Dd + d;

    float s = 0.0f, A = 1.0f;
    #pragma unroll 8
    for (int k = 0; k < LCH; k++) {
        size_t idx = base + (size_t)k * Dd;
        float lam = g_lam[idx];
        float xv  = X[idx];
        s = fmaf(lam, s - xv, xv);   // s = lam*s + (1-lam)*x
        A *= lam;
    }
    const int ch = b * Dd + d;
    g_A[c * CHN + ch] = A;
    g_S[c * CHN + ch] = s;
}

// ---------------------------------------------------------------------------
// Scan phase 2: sequential combine of 32 chunk summaries per channel (tiny).
// ---------------------------------------------------------------------------
__global__ __launch_bounds__(256) void scan_phase2()
{
    const int ch = blockIdx.x * 256 + threadIdx.x;
    float s = 0.0f;
    #pragma unroll
    for (int c = 0; c < NCH; c++) {
        g_P[c * CHN + ch] = s;
        s = fmaf(g_A[c * CHN + ch], s, g_S[c * CHN + ch]);
    }
}

// ---------------------------------------------------------------------------
// Scan phase 3: re-scan each chunk starting from its prefix; write output.
// ---------------------------------------------------------------------------
__global__ __launch_bounds__(256) void scan_phase3(const float* __restrict__ X,
                                                   float* __restrict__ out)
{
    const int d = blockIdx.x * 256 + threadIdx.x;
    const int b = blockIdx.y;
    const int c = blockIdx.z;
    const int ch = b * Dd + d;
    size_t base = ((size_t)(b * Kk + c * LCH)) * Dd + d;

    float s = g_P[c * CHN + ch];
    #pragma unroll 8
    for (int k = 0; k < LCH; k++) {
        size_t idx = base + (size_t)k * Dd;
        float lam = g_lam[idx];
        float xv  = X[idx];
        s = fmaf(lam, s - xv, xv);
        out[idx] = s;
    }
}

// ---------------------------------------------------------------------------
extern "C" void kernel_launch(void* const* d_in, const int* in_sizes, int n_in,
                              void* d_out, int out_size)
{
    const float* X    = (const float*)d_in[0];  // [B,K,D]
    const float* W    = (const float*)d_in[1];  // [D,D]
    const float* bias = (const float*)d_in[2];  // [D]
    float* out        = (float*)d_out;          // [B,K,D]

    // fp16 conversion passes
    __half* Xh; cudaGetSymbolAddress((void**)&Xh, g_Xh);
    __half* Wh; cudaGetSymbolAddress((void**)&Wh, g_Wh);
    f2h_kernel<<<1024, 256>>>((const float4*)X, (uint2*)Xh, (Mm * Dd) / 4);
    f2h_kernel<<<256, 256>>>((const float4*)W, (uint2*)Wh, (Dd * Dd) / 4);

    const int smem_bytes = SMEM_HALVES * (int)sizeof(__half);   // 120 KB
    cudaFuncSetAttribute(gemm_sigmoid_f16,
                         cudaFuncAttributeMaxDynamicSharedMemorySize, smem_bytes);

    dim3 gemm_grid(Dd / BN, Mm / BM);           // (4, 256)
    gemm_sigmoid_f16<<<gemm_grid, 256, smem_bytes>>>(bias);

    dim3 scan_grid(Dd / 256, Bb, NCH);          // (4, 4, 32)
    scan_phase1<<<scan_grid, 256>>>(X);
    scan_phase2<<<CHN / 256, 256>>>();
    scan_phase3<<<scan_grid, 256>>>(X, out);
}